// round 6
// baseline (speedup 1.0000x reference)
#include <cuda_runtime.h>
#include <cuda_bf16.h>
#include <cstdint>

// LinearAttention: out[n,l,h,e] = (phi(Q)@KV) * Z, phi = elu+1 (vlen cancels)
//   KV = sum_s phi(K)[s,d] * V[s,e] ;  Z = 1/(phi(Q).Ksum + 1e-6)
//
// R6: BOTH phases on mma.sync bf16 (m16n8k16) with 2-term Dekker split.
//  p1: D[e_ext][d] = V_ext^T @ phiK  via ldmatrix.x4.trans from natural
//      [s][cols] smem (A = V_ext, M=80 incl. ones-col 64 -> row 64 = Ksum).
//      Output rows 0..64 are exactly p2's B operand ([e][d] + Ksum row).
//  p2: unchanged from R5 except it reads p1's fused output.

#define DEV_INLINE __device__ __forceinline__

constexpr int Hh = 8, Dd = 64, Ll = 8192, Ss = 8192, Nn = 4;
constexpr int NH = Nn * Hh;                // 32
constexpr int ROWSTRIDE = Hh * Dd;         // 512
constexpr int P1_CHUNKS = 32;
constexpr int P1_SCHUNK = Ss / P1_CHUNKS;  // 256 s per CTA
constexpr int KV_PITCH = 65 * 64;          // 4160 floats per (nh) KV_ext

// scratch: partial KV_ext [chunk][nh][e(0..64)][d]
__device__ __align__(16) float g_part_kv[(size_t)P1_CHUNKS * NH * KV_PITCH];
__device__ __align__(16) float g_kv[NH * KV_PITCH];

using u64 = unsigned long long;

DEV_INLINE float featmap(float x) { return __expf(fminf(x, 0.f)) + fmaxf(x, 0.f); }
DEV_INLINE unsigned bf2u(__nv_bfloat162 v) { return *reinterpret_cast<unsigned*>(&v); }
// Dekker split of (a,b) -> bf16x2 hi word + lo word
DEV_INLINE void bsplit2(float a, float b, unsigned& h, unsigned& l) {
    __nv_bfloat162 hv = __floats2bfloat162_rn(a, b);
    float2 hf = __bfloat1622float2(hv);
    __nv_bfloat162 lv = __floats2bfloat162_rn(a - hf.x, b - hf.y);
    h = bf2u(hv); l = bf2u(lv);
}
DEV_INLINE uint32_t smem_u32(const void* p) {
    uint32_t a;
    asm("{ .reg .u64 t; cvta.to.shared.u64 t, %1; cvt.u32.u64 %0, t; }"
        : "=r"(a) : "l"(p));
    return a;
}
DEV_INLINE void mma_bf16(float4& c, const uint32_t a[4], uint32_t b0, uint32_t b1) {
    asm volatile(
        "mma.sync.aligned.m16n8k16.row.col.f32.bf16.bf16.f32 "
        "{%0,%1,%2,%3}, {%4,%5,%6,%7}, {%8,%9}, {%0,%1,%2,%3};"
        : "+f"(c.x), "+f"(c.y), "+f"(c.z), "+f"(c.w)
        : "r"(a[0]), "r"(a[1]), "r"(a[2]), "r"(a[3]), "r"(b0), "r"(b1));
}
DEV_INLINE void ldm4t(uint32_t* r, uint32_t addr) {
    asm volatile(
        "ldmatrix.sync.aligned.m8n8.x4.trans.shared.b16 {%0,%1,%2,%3}, [%4];"
        : "=r"(r[0]), "=r"(r[1]), "=r"(r[2]), "=r"(r[3]) : "r"(addr));
}

// ============================================================================
// Phase 1: HMMA. Block = 128 thr / 4 warps. Grid (P1_CHUNKS, NH).
// Per 64-s tile: stage phiK hi/lo [s][64] (pitch 144B) + V hi/lo [s][80+pad]
// (pitch 176B, col 64 = ones), then ldmatrix.trans fragments + 3-term MMA.
// Warp w owns d-cols [w*16, w*16+16). acc = D[e=80][d].
// ============================================================================
__global__ __launch_bounds__(128) void p1_kernel(const float* __restrict__ keys,
                                                 const float* __restrict__ values) {
    __shared__ __align__(16) char KH[64 * 144];
    __shared__ __align__(16) char KL[64 * 144];
    __shared__ __align__(16) char VH[64 * 176];
    __shared__ __align__(16) char VL[64 * 176];

    const int t   = threadIdx.x;
    const int wid = t >> 5, lid = t & 31;
    const int grp = lid >> 3, r8 = lid & 7;
    const int nh  = blockIdx.y;
    const int n   = nh >> 3, h = nh & 7;
    const int s0  = blockIdx.x * P1_SCHUNK;
    const int n0  = wid * 16;

    const uint32_t KHu = smem_u32(KH), KLu = smem_u32(KL);
    const uint32_t VHu = smem_u32(VH), VLu = smem_u32(VL);

    // per-lane ldmatrix offsets (derived block addressing, .trans):
    // A (from V): r0=(m0-7,k0-7) r1=(m8-15,k0-7) r2=(m0-7,k8-15) r3=(m8-15,k8-15)
    //   -> src rows s += (grp&2)?8:0 ; src cols e += (grp&1)?8:0
    const uint32_t aoff = (uint32_t)((r8 + ((grp & 2) ? 8 : 0)) * 176 +
                                     ((grp & 1) ? 8 : 0) * 2);
    // B (from K): r0=(k0-7,n0-7) r1=(k8-15,n0-7) r2=(k0-7,n8-15) r3=(k8-15,n8-15)
    //   -> src rows s += (grp&1)?8:0 ; src cols d += (grp&2)?8:0
    const uint32_t boff = (uint32_t)((r8 + ((grp & 1) ? 8 : 0)) * 144 +
                                     ((grp & 2) ? 8 : 0) * 2);

    // init V ext cols 64..79 once (col 64 = 1.0 hi / 0 lo; 65..79 = 0)
#pragma unroll
    for (int j = 0; j < 2; ++j) {
        int idx = t + 128 * j;          // 0..255
        int s = idx >> 2, c4e = 16 + (idx & 3);
        u64 hv = ((idx & 3) == 0) ? 0x3F80ull : 0ull;   // bf16 1.0 in col 64
        *(u64*)(VH + s * 176 + c4e * 8) = hv;
        *(u64*)(VL + s * 176 + c4e * 8) = 0ull;
    }

    float4 acc[5][2];
#pragma unroll
    for (int mt = 0; mt < 5; ++mt)
#pragma unroll
        for (int nt = 0; nt < 2; ++nt) acc[mt][nt] = make_float4(0.f, 0.f, 0.f, 0.f);

    for (int tile = 0; tile < P1_SCHUNK / 64; ++tile) {
        // ---- stage 64 s-rows: K (phi + split), V (split) ----
        const float* kb = keys   + ((size_t)(n * Ss + s0 + tile * 64) * ROWSTRIDE + h * Dd);
        const float* vb = values + ((size_t)(n * Ss + s0 + tile * 64) * ROWSTRIDE + h * Dd);
#pragma unroll
        for (int j = 0; j < 8; ++j) {
            int idx = t + 128 * j;
            int s = idx >> 4, c4 = idx & 15;
            float4 kq = *(const float4*)(kb + (size_t)s * ROWSTRIDE + c4 * 4);
            float4 vq = *(const float4*)(vb + (size_t)s * ROWSTRIDE + c4 * 4);
            float fx = featmap(kq.x), fy = featmap(kq.y);
            float fz = featmap(kq.z), fw = featmap(kq.w);
            unsigned h0, l0_, h1, l1;
            bsplit2(fx, fy, h0, l0_);
            bsplit2(fz, fw, h1, l1);
            *(u64*)(KH + s * 144 + c4 * 8) = ((u64)h1 << 32) | h0;
            *(u64*)(KL + s * 144 + c4 * 8) = ((u64)l1 << 32) | l0_;
            bsplit2(vq.x, vq.y, h0, l0_);
            bsplit2(vq.z, vq.w, h1, l1);
            *(u64*)(VH + s * 176 + c4 * 8) = ((u64)h1 << 32) | h0;
            *(u64*)(VL + s * 176 + c4 * 8) = ((u64)l1 << 32) | l0_;
        }
        __syncthreads();

        // ---- MMA: 4 k-tiles of 16 s ----
#pragma unroll
        for (int kt = 0; kt < 4; ++kt) {
            uint32_t bh[4], bl[4];
            ldm4t(bh, KHu + (uint32_t)(kt * 16 * 144 + n0 * 2) + boff);
            ldm4t(bl, KLu + (uint32_t)(kt * 16 * 144 + n0 * 2) + boff);
#pragma unroll
            for (int mt = 0; mt < 5; ++mt) {
                uint32_t ah[4], al[4];
                ldm4t(ah, VHu + (uint32_t)(kt * 16 * 176 + mt * 32) + aoff);
                ldm4t(al, VLu + (uint32_t)(kt * 16 * 176 + mt * 32) + aoff);
#pragma unroll
                for (int nt = 0; nt < 2; ++nt) {
                    mma_bf16(acc[mt][nt], ah, bh[nt * 2], bh[nt * 2 + 1]);
                    mma_bf16(acc[mt][nt], ah, bl[nt * 2], bl[nt * 2 + 1]);
                    mma_bf16(acc[mt][nt], al, bh[nt * 2], bh[nt * 2 + 1]);
                }
            }
        }
        __syncthreads();
    }

    // ---- writeback partial D[e][d], rows e<65 only ----
    const int g = lid >> 2, tg = lid & 3;
    float* base = g_part_kv + ((size_t)blockIdx.x * NH + nh) * KV_PITCH;
#pragma unroll
    for (int mt = 0; mt < 5; ++mt)
#pragma unroll
        for (int nt = 0; nt < 2; ++nt) {
            const int e0 = mt * 16 + g;
            const int d  = n0 + nt * 8 + tg * 2;
            if (mt < 4) {
                *(float2*)(base + e0 * 64 + d)       = make_float2(acc[mt][nt].x, acc[mt][nt].y);
                *(float2*)(base + (e0 + 8) * 64 + d) = make_float2(acc[mt][nt].z, acc[mt][nt].w);
            } else if (g == 0) {   // e = 64 (Ksum row)
                *(float2*)(base + 64 * 64 + d)       = make_float2(acc[mt][nt].x, acc[mt][nt].y);
            }
        }
}

// ============================================================================
// Phase 1b: fixed-order reduction over chunks
// ============================================================================
__global__ void reduce_kernel() {
    int i = blockIdx.x * 256 + threadIdx.x;
    if (i < NH * (KV_PITCH / 4)) {
        float4 s = make_float4(0.f, 0.f, 0.f, 0.f);
#pragma unroll
        for (int c = 0; c < P1_CHUNKS; c++) {
            float4 p = *(const float4*)(g_part_kv + (size_t)c * NH * KV_PITCH + i * 4);
            s.x += p.x; s.y += p.y; s.z += p.z; s.w += p.w;
        }
        *(float4*)(g_kv + i * 4) = s;
    }
}

// ============================================================================
// Phase 2 (R5, validated): mma.sync bf16, Z = B row 64.
// ============================================================================
constexpr uint32_t QH_OFF = 0;          // 128 rows x 144 B
constexpr uint32_t QL_OFF = 18432;
constexpr uint32_t BH_OFF = 36864;      // 72 rows x 144 B
constexpr uint32_t BL_OFF = 47232;
constexpr uint32_t P2_DSM = 57600;

__global__ __launch_bounds__(128) void p2_kernel(const float* __restrict__ queries,
                                                 float* __restrict__ out) {
    extern __shared__ __align__(16) char sm[];
    char* QH = sm + QH_OFF; char* QL = sm + QL_OFF;
    char* BH = sm + BH_OFF; char* BL = sm + BL_OFF;

    const int t    = threadIdx.x;
    const int wid  = t >> 5, lane = t & 31;
    const int g    = lane >> 2, tg = lane & 3;
    const int nh   = blockIdx.y;
    const int n    = nh >> 3, h = nh & 7;
    const int l0   = blockIdx.x * 128;

    // ---- stage B: rows 0..64 = KV_ext (row 64 = Ksum), 65..71 = 0 ----
    if (t < 72) {
        const float* src = g_kv + (size_t)nh * KV_PITCH + t * 64;
#pragma unroll
        for (int c4 = 0; c4 < 16; ++c4) {
            float4 v = (t <= 64) ? *(const float4*)(src + c4 * 4)
                                 : make_float4(0.f, 0.f, 0.f, 0.f);
            unsigned hxy, lxy, hzw, lzw;
            bsplit2(v.x, v.y, hxy, lxy);
            bsplit2(v.z, v.w, hzw, lzw);
            *(u64*)(BH + t * 144 + c4 * 8) = ((u64)hzw << 32) | hxy;
            *(u64*)(BL + t * 144 + c4 * 8) = ((u64)lzw << 32) | lxy;
        }
    }

    // ---- stage Q: 128 rows x 64 cols, phi + split ----
    const float* qbase = queries + ((size_t)(n * Ll + l0) * ROWSTRIDE + h * Dd);
#pragma unroll
    for (int k2 = 0; k2 < 16; ++k2) {
        int idx = t + 128 * k2;
        int row = idx >> 4, c4 = idx & 15;
        float4 qv = *(const float4*)(qbase + (size_t)row * ROWSTRIDE + c4 * 4);
        float fx = featmap(qv.x), fy = featmap(qv.y);
        float fz = featmap(qv.z), fw = featmap(qv.w);
        unsigned hxy, lxy, hzw, lzw;
        bsplit2(fx, fy, hxy, lxy);
        bsplit2(fz, fw, hzw, lzw);
        *(u64*)(QH + row * 144 + c4 * 8) = ((u64)hzw << 32) | hxy;
        *(u64*)(QL + row * 144 + c4 * 8) = ((u64)lzw << 32) | lxy;
    }
    __syncthreads();

    float4 C[2][9];
#pragma unroll
    for (int mt = 0; mt < 2; ++mt)
#pragma unroll
        for (int nt = 0; nt < 9; ++nt) C[mt][nt] = make_float4(0.f, 0.f, 0.f, 0.f);

    const int cb = tg * 4;
#pragma unroll
    for (int kt = 0; kt < 4; ++kt) {
        const int kb = kt * 32 + cb;
        uint32_t ah[2][4], al[2][4];
#pragma unroll
        for (int mt = 0; mt < 2; ++mt) {
            const int r0 = wid * 32 + mt * 16 + g;
            ah[mt][0] = *(const uint32_t*)(QH + r0 * 144 + kb);
            ah[mt][1] = *(const uint32_t*)(QH + (r0 + 8) * 144 + kb);
            ah[mt][2] = *(const uint32_t*)(QH + r0 * 144 + kb + 16);
            ah[mt][3] = *(const uint32_t*)(QH + (r0 + 8) * 144 + kb + 16);
            al[mt][0] = *(const uint32_t*)(QL + r0 * 144 + kb);
            al[mt][1] = *(const uint32_t*)(QL + (r0 + 8) * 144 + kb);
            al[mt][2] = *(const uint32_t*)(QL + r0 * 144 + kb + 16);
            al[mt][3] = *(const uint32_t*)(QL + (r0 + 8) * 144 + kb + 16);
        }
#pragma unroll
        for (int nt = 0; nt < 9; ++nt) {
            const int e0 = nt * 8 + g;
            uint32_t bh0 = *(const uint32_t*)(BH + e0 * 144 + kb);
            uint32_t bh1 = *(const uint32_t*)(BH + e0 * 144 + kb + 16);
            uint32_t bl0 = *(const uint32_t*)(BL + e0 * 144 + kb);
            uint32_t bl1 = *(const uint32_t*)(BL + e0 * 144 + kb + 16);
#pragma unroll
            for (int mt = 0; mt < 2; ++mt) {
                mma_bf16(C[mt][nt], ah[mt], bh0, bh1);
                mma_bf16(C[mt][nt], ah[mt], bl0, bl1);
                mma_bf16(C[mt][nt], al[mt], bh0, bh1);
            }
        }
    }

    // ---- epilogue: Z = D[:,64] (n-tile 8, quad leader lanes) ----
#pragma unroll
    for (int mt = 0; mt < 2; ++mt) {
        const int src = (lane >> 2) << 2;
        float z0 = __shfl_sync(0xFFFFFFFFu, C[mt][8].x, src);
        float z1 = __shfl_sync(0xFFFFFFFFu, C[mt][8].z, src);
        float i0 = 1.0f / (z0 + 1e-6f);
        float i1 = 1.0f / (z1 + 1e-6f);
        const int r0 = l0 + wid * 32 + mt * 16 + g;
        float* p0 = out + ((size_t)(n * Ll + r0) * Hh + h) * Dd;
        float* p1 = p0 + (size_t)8 * ROWSTRIDE;
#pragma unroll
        for (int nt = 0; nt < 8; ++nt) {
            const int col = nt * 8 + tg * 2;
            *(float2*)(p0 + col) = make_float2(C[mt][nt].x * i0, C[mt][nt].y * i0);
            *(float2*)(p1 + col) = make_float2(C[mt][nt].z * i1, C[mt][nt].w * i1);
        }
    }
}

// ============================================================================
extern "C" void kernel_launch(void* const* d_in, const int* in_sizes, int n_in,
                              void* d_out, int out_size) {
    const float* q = (const float*)d_in[0];
    const float* k = (const float*)d_in[1];
    const float* v = (const float*)d_in[2];
    float* o = (float*)d_out;
    (void)in_sizes; (void)n_in; (void)out_size;

    cudaFuncSetAttribute(p2_kernel, cudaFuncAttributeMaxDynamicSharedMemorySize, P2_DSM);

    p1_kernel<<<dim3(P1_CHUNKS, NH), 128>>>(k, v);
    reduce_kernel<<<(NH * (KV_PITCH / 4) + 255) / 256, 256>>>();
    p2_kernel<<<dim3(Ll / 128, NH), 128, P2_DSM>>>(q, o);
}

// round 7
// speedup vs baseline: 1.4565x; 1.4565x over previous
#include <cuda_runtime.h>
#include <cuda_bf16.h>
#include <cstdint>

// LinearAttention: out[n,l,h,e] = (phi(Q)@KV) * Z, phi = elu+1 (vlen cancels)
//   KV = sum_s phi(K)[s,d] * V[s,e] ;  Z = 1/(phi(Q).Ksum + 1e-6)
//
// R7: both phases HMMA (mma.sync m16n8k16 bf16, 2-term Dekker split), now
// properly pipelined: double-buffered smem + register prefetch of the next
// gmem tile issued before the MMA loop (R3's scheme, lost in R6).
//  p1: 256thr/8 warps, warp = one 8-col n-group (ldmatrix.x2.trans B),
//      all 5 m-tiles (M=80 incl. ones-col 64 -> Ksum row). 60 MMA/warp/tile.
//  p2: 256thr/8 warps, warp = one m16 l-tile, 9 n-tiles (Z = col 64);
//      2 l-tiles per CTA, Q double-buffered, B staged once.

#define DEV_INLINE __device__ __forceinline__

constexpr int Hh = 8, Dd = 64, Ll = 8192, Ss = 8192, Nn = 4;
constexpr int NH = Nn * Hh;                // 32
constexpr int ROWSTRIDE = Hh * Dd;         // 512
constexpr int P1_CHUNKS = 32;
constexpr int P1_SCHUNK = Ss / P1_CHUNKS;  // 256 s per CTA (4 tiles of 64)
constexpr int KV_PITCH = 65 * 64;          // 4160 floats per (nh) KV_ext

__device__ __align__(16) float g_part_kv[(size_t)P1_CHUNKS * NH * KV_PITCH];
__device__ __align__(16) float g_kv[NH * KV_PITCH];

using u64 = unsigned long long;

DEV_INLINE float featmap(float x) { return __expf(fminf(x, 0.f)) + fmaxf(x, 0.f); }
DEV_INLINE unsigned bf2u(__nv_bfloat162 v) { return *reinterpret_cast<unsigned*>(&v); }
DEV_INLINE void bsplit2(float a, float b, unsigned& h, unsigned& l) {
    __nv_bfloat162 hv = __floats2bfloat162_rn(a, b);
    float2 hf = __bfloat1622float2(hv);
    __nv_bfloat162 lv = __floats2bfloat162_rn(a - hf.x, b - hf.y);
    h = bf2u(hv); l = bf2u(lv);
}
DEV_INLINE uint32_t smem_u32(const void* p) {
    uint32_t a;
    asm("{ .reg .u64 t; cvta.to.shared.u64 t, %1; cvt.u32.u64 %0, t; }"
        : "=r"(a) : "l"(p));
    return a;
}
DEV_INLINE void mma_bf16(float4& c, const uint32_t a[4], uint32_t b0, uint32_t b1) {
    asm volatile(
        "mma.sync.aligned.m16n8k16.row.col.f32.bf16.bf16.f32 "
        "{%0,%1,%2,%3}, {%4,%5,%6,%7}, {%8,%9}, {%0,%1,%2,%3};"
        : "+f"(c.x), "+f"(c.y), "+f"(c.z), "+f"(c.w)
        : "r"(a[0]), "r"(a[1]), "r"(a[2]), "r"(a[3]), "r"(b0), "r"(b1));
}
DEV_INLINE void ldm4t(uint32_t* r, uint32_t addr) {
    asm volatile(
        "ldmatrix.sync.aligned.m8n8.x4.trans.shared.b16 {%0,%1,%2,%3}, [%4];"
        : "=r"(r[0]), "=r"(r[1]), "=r"(r[2]), "=r"(r[3]) : "r"(addr));
}
DEV_INLINE void ldm2t(uint32_t* r, uint32_t addr) {
    asm volatile(
        "ldmatrix.sync.aligned.m8n8.x2.trans.shared.b16 {%0,%1}, [%2];"
        : "=r"(r[0]), "=r"(r[1]) : "r"(addr));
}

// ---- p1 dynamic smem layout (double-buffered) ----
constexpr uint32_t P1_KH = 0;          // 2 x 64x144
constexpr uint32_t P1_KL = 18432;
constexpr uint32_t P1_VH = 36864;      // 2 x 64x176
constexpr uint32_t P1_VL = 59392;
constexpr uint32_t P1_DSM = 81920;

// ============================================================================
// Phase 1: D[e_ext][d] = V_ext^T @ phiK. 256 thr / 8 warps.
// Warp w: n-cols [w*8, w*8+8), m-tiles 0..4 (e rows; mt4 row64 = Ksum).
// Grid (P1_CHUNKS, NH).
// ============================================================================
__global__ __launch_bounds__(256) void p1_kernel(const float* __restrict__ keys,
                                                 const float* __restrict__ values) {
    extern __shared__ __align__(16) char sm1[];

    const int t   = threadIdx.x;
    const int wid = t >> 5, lid = t & 31;
    const int grp = lid >> 3, r8 = lid & 7;
    const int g   = lid >> 2, tg = lid & 3;
    const int nh  = blockIdx.y;
    const int n   = nh >> 3, h = nh & 7;
    const int s0  = blockIdx.x * P1_SCHUNK;
    const int n0  = wid * 8;

    const uint32_t smb = smem_u32(sm1);
    // ldmatrix lane offsets (.trans):
    // A (V, m16k16 x4): rows s += (grp&2)?8:0 ; cols e += (grp&1)?8:0
    const uint32_t aoff = (uint32_t)((r8 + ((grp & 2) ? 8 : 0)) * 176 +
                                     ((grp & 1) ? 8 : 0) * 2);
    // B (K, k16n8 x2): rows s += (grp&1)?8:0 (lanes 0..15 used)
    const uint32_t boff = (uint32_t)((r8 + ((grp & 1) ? 8 : 0)) * 144);

    // init ones-columns (e 64..79) in BOTH V buffers
#pragma unroll
    for (int j = 0; j < 2; ++j) {
        int idx = t + 256 * j;                 // 512 items
        int b = idx >> 8, rr = (idx & 255) >> 2, c4e = 16 + (idx & 3);
        u64 hv = ((idx & 3) == 0) ? 0x3F80ull : 0ull;  // bf16 1.0 at col 64
        *(u64*)(sm1 + P1_VH + b * 11264 + rr * 176 + c4e * 8) = hv;
        *(u64*)(sm1 + P1_VL + b * 11264 + rr * 176 + c4e * 8) = 0ull;
    }

    float4 acc[5];
#pragma unroll
    for (int mt = 0; mt < 5; ++mt) acc[mt] = make_float4(0.f, 0.f, 0.f, 0.f);

    // staging slots: idx = t + 256j (j<4) -> row idx>>4 (0..63), c4 idx&15
    int rr_[4], cc_[4];
#pragma unroll
    for (int j = 0; j < 4; ++j) { int idx = t + 256 * j; rr_[j] = idx >> 4; cc_[j] = idx & 15; }

    float4 bk[4], bv[4];
#pragma unroll
    for (int j = 0; j < 4; ++j) {
        size_t row = (size_t)(n * Ss + s0 + rr_[j]);
        bk[j] = *(const float4*)(keys   + row * ROWSTRIDE + h * Dd + cc_[j] * 4);
        bv[j] = *(const float4*)(values + row * ROWSTRIDE + h * Dd + cc_[j] * 4);
    }

    for (int tile = 0; tile < P1_SCHUNK / 64; ++tile) {
        const int b = tile & 1;
        char* KH = sm1 + P1_KH + b * 9216;
        char* KL = sm1 + P1_KL + b * 9216;
        char* VH = sm1 + P1_VH + b * 11264;
        char* VL = sm1 + P1_VL + b * 11264;
        // convert + store staged regs
#pragma unroll
        for (int j = 0; j < 4; ++j) {
            unsigned h0, l0_, h1, l1;
            float fx = featmap(bk[j].x), fy = featmap(bk[j].y);
            float fz = featmap(bk[j].z), fw = featmap(bk[j].w);
            bsplit2(fx, fy, h0, l0_);
            bsplit2(fz, fw, h1, l1);
            *(u64*)(KH + rr_[j] * 144 + cc_[j] * 8) = ((u64)h1 << 32) | h0;
            *(u64*)(KL + rr_[j] * 144 + cc_[j] * 8) = ((u64)l1 << 32) | l0_;
            bsplit2(bv[j].x, bv[j].y, h0, l0_);
            bsplit2(bv[j].z, bv[j].w, h1, l1);
            *(u64*)(VH + rr_[j] * 176 + cc_[j] * 8) = ((u64)h1 << 32) | h0;
            *(u64*)(VL + rr_[j] * 176 + cc_[j] * 8) = ((u64)l1 << 32) | l0_;
        }
        __syncthreads();

        // prefetch next tile (LDGs in flight under the MMA loop)
        if (tile + 1 < P1_SCHUNK / 64) {
#pragma unroll
            for (int j = 0; j < 4; ++j) {
                size_t row = (size_t)(n * Ss + s0 + (tile + 1) * 64 + rr_[j]);
                bk[j] = *(const float4*)(keys   + row * ROWSTRIDE + h * Dd + cc_[j] * 4);
                bv[j] = *(const float4*)(values + row * ROWSTRIDE + h * Dd + cc_[j] * 4);
            }
        }

        const uint32_t KHu = smb + P1_KH + b * 9216;
        const uint32_t KLu = smb + P1_KL + b * 9216;
        const uint32_t VHu = smb + P1_VH + b * 11264;
        const uint32_t VLu = smb + P1_VL + b * 11264;
#pragma unroll
        for (int kt = 0; kt < 4; ++kt) {
            uint32_t bh[2], bl[2];
            ldm2t(bh, KHu + (uint32_t)(kt * 16 * 144 + n0 * 2) + boff);
            ldm2t(bl, KLu + (uint32_t)(kt * 16 * 144 + n0 * 2) + boff);
#pragma unroll
            for (int mt = 0; mt < 5; ++mt) {
                uint32_t ah[4], al[4];
                ldm4t(ah, VHu + (uint32_t)(kt * 16 * 176 + mt * 32) + aoff);
                ldm4t(al, VLu + (uint32_t)(kt * 16 * 176 + mt * 32) + aoff);
                mma_bf16(acc[mt], ah, bh[0], bh[1]);
                mma_bf16(acc[mt], ah, bl[0], bl[1]);
                mma_bf16(acc[mt], al, bh[0], bh[1]);
            }
        }
        // no trailing sync: next store targets the other buffer; the sync at
        // the top of the next iteration protects buffer reuse (t+2 vs t).
    }

    // writeback partial: rows e<65
    float* base = g_part_kv + ((size_t)blockIdx.x * NH + nh) * KV_PITCH;
#pragma unroll
    for (int mt = 0; mt < 5; ++mt) {
        const int e0 = mt * 16 + g;
        const int d  = n0 + tg * 2;
        if (mt < 4) {
            *(float2*)(base + e0 * 64 + d)       = make_float2(acc[mt].x, acc[mt].y);
            *(float2*)(base + (e0 + 8) * 64 + d) = make_float2(acc[mt].z, acc[mt].w);
        } else if (g == 0) {   // e = 64 (Ksum row)
            *(float2*)(base + 64 * 64 + d)       = make_float2(acc[mt].x, acc[mt].y);
        }
    }
}

// ============================================================================
// Phase 1b: fixed-order reduction over chunks
// ============================================================================
__global__ void reduce_kernel() {
    int i = blockIdx.x * 256 + threadIdx.x;
    if (i < NH * (KV_PITCH / 4)) {
        float4 s = make_float4(0.f, 0.f, 0.f, 0.f);
#pragma unroll
        for (int c = 0; c < P1_CHUNKS; c++) {
            float4 p = *(const float4*)(g_part_kv + (size_t)c * NH * KV_PITCH + i * 4);
            s.x += p.x; s.y += p.y; s.z += p.z; s.w += p.w;
        }
        *(float4*)(g_kv + i * 4) = s;
    }
}

// ---- p2 dynamic smem layout ----
constexpr uint32_t P2_QH = 0;           // 2 x 128x144
constexpr uint32_t P2_QL = 36864;
constexpr uint32_t P2_BH = 73728;       // 72x144
constexpr uint32_t P2_BL = 84096;
constexpr uint32_t P2_DSM = 94464;

// ============================================================================
// Phase 2: out = (phiQ @ KV_ext) * Z. 256 thr / 8 warps, warp = m16 tile.
// 2 l-tiles per CTA (Q double-buffered, register prefetch). Grid (32, NH).
// ============================================================================
__global__ __launch_bounds__(256) void p2_kernel(const float* __restrict__ queries,
                                                 float* __restrict__ out) {
    extern __shared__ __align__(16) char sm2[];
    char* BH = sm2 + P2_BH; char* BL = sm2 + P2_BL;

    const int t    = threadIdx.x;
    const int wid  = t >> 5, lane = t & 31;
    const int g    = lane >> 2, tg = lane & 3;
    const int nh   = blockIdx.y;
    const int n    = nh >> 3, h = nh & 7;
    const int lbase = blockIdx.x * 256;

    // stage B once: rows 0..64 = KV_ext (row 64 = Ksum), 65..71 = 0
    if (t < 72) {
        const float* src = g_kv + (size_t)nh * KV_PITCH + t * 64;
#pragma unroll
        for (int c4 = 0; c4 < 16; ++c4) {
            float4 v = (t <= 64) ? *(const float4*)(src + c4 * 4)
                                 : make_float4(0.f, 0.f, 0.f, 0.f);
            unsigned hxy, lxy, hzw, lzw;
            bsplit2(v.x, v.y, hxy, lxy);
            bsplit2(v.z, v.w, hzw, lzw);
            *(u64*)(BH + t * 144 + c4 * 8) = ((u64)hzw << 32) | hxy;
            *(u64*)(BL + t * 144 + c4 * 8) = ((u64)lzw << 32) | lxy;
        }
    }

    // staging slots: idx = t + 256*k2 (k2<8) -> row idx>>4 (0..127), c4 idx&15
    int qr[8], qc[8];
#pragma unroll
    for (int k2 = 0; k2 < 8; ++k2) { int idx = t + 256 * k2; qr[k2] = idx >> 4; qc[k2] = idx & 15; }

    float4 bq[8];
#pragma unroll
    for (int k2 = 0; k2 < 8; ++k2) {
        size_t row = (size_t)(n * Ll + lbase + qr[k2]);
        bq[k2] = *(const float4*)(queries + row * ROWSTRIDE + h * Dd + qc[k2] * 4);
    }

    for (int tile = 0; tile < 2; ++tile) {
        char* QH = sm2 + P2_QH + tile * 18432;
        char* QL = sm2 + P2_QL + tile * 18432;
#pragma unroll
        for (int k2 = 0; k2 < 8; ++k2) {
            unsigned hxy, lxy, hzw, lzw;
            float fx = featmap(bq[k2].x), fy = featmap(bq[k2].y);
            float fz = featmap(bq[k2].z), fw = featmap(bq[k2].w);
            bsplit2(fx, fy, hxy, lxy);
            bsplit2(fz, fw, hzw, lzw);
            *(u64*)(QH + qr[k2] * 144 + qc[k2] * 8) = ((u64)hzw << 32) | hxy;
            *(u64*)(QL + qr[k2] * 144 + qc[k2] * 8) = ((u64)lzw << 32) | lxy;
        }
        __syncthreads();

        if (tile == 0) {
#pragma unroll
            for (int k2 = 0; k2 < 8; ++k2) {
                size_t row = (size_t)(n * Ll + lbase + 128 + qr[k2]);
                bq[k2] = *(const float4*)(queries + row * ROWSTRIDE + h * Dd + qc[k2] * 4);
            }
        }

        float4 C[9];
#pragma unroll
        for (int nt = 0; nt < 9; ++nt) C[nt] = make_float4(0.f, 0.f, 0.f, 0.f);

        const int cb = tg * 4;
#pragma unroll
        for (int kt = 0; kt < 4; ++kt) {
            const int kb = kt * 32 + cb;
            const int r0 = wid * 16 + g;
            uint32_t ah[4], al[4];
            ah[0] = *(const uint32_t*)(QH + r0 * 144 + kb);
            ah[1] = *(const uint32_t*)(QH + (r0 + 8) * 144 + kb);
            ah[2] = *(const uint32_t*)(QH + r0 * 144 + kb + 16);
            ah[3] = *(const uint32_t*)(QH + (r0 + 8) * 144 + kb + 16);
            al[0] = *(const uint32_t*)(QL + r0 * 144 + kb);
            al[1] = *(const uint32_t*)(QL + (r0 + 8) * 144 + kb);
            al[2] = *(const uint32_t*)(QL + r0 * 144 + kb + 16);
            al[3] = *(const uint32_t*)(QL + (r0 + 8) * 144 + kb + 16);
#pragma unroll
            for (int nt = 0; nt < 9; ++nt) {
                const int e0 = nt * 8 + g;
                uint32_t bh0 = *(const uint32_t*)(BH + e0 * 144 + kb);
                uint32_t bh1 = *(const uint32_t*)(BH + e0 * 144 + kb + 16);
                uint32_t bl0 = *(const uint32_t*)(BL + e0 * 144 + kb);
                uint32_t bl1 = *(const uint32_t*)(BL + e0 * 144 + kb + 16);
                mma_bf16(C[nt], ah, bh0, bh1);
                mma_bf16(C[nt], ah, bl0, bl1);
                mma_bf16(C[nt], al, bh0, bh1);
            }
        }

        // epilogue: Z = C[8] (col 64 -> quad leader lanes)
        const int src = (lane >> 2) << 2;
        float z0 = __shfl_sync(0xFFFFFFFFu, C[8].x, src);
        float z1 = __shfl_sync(0xFFFFFFFFu, C[8].z, src);
        float i0 = 1.0f / (z0 + 1e-6f);
        float i1 = 1.0f / (z1 + 1e-6f);
        const int r = lbase + tile * 128 + wid * 16 + g;
        float* p0 = out + ((size_t)(n * Ll + r) * Hh + h) * Dd;
        float* p1 = p0 + (size_t)8 * ROWSTRIDE;
#pragma unroll
        for (int nt = 0; nt < 8; ++nt) {
            const int col = nt * 8 + tg * 2;
            *(float2*)(p0 + col) = make_float2(C[nt].x * i0, C[nt].y * i0);
            *(float2*)(p1 + col) = make_float2(C[nt].z * i1, C[nt].w * i1);
        }
        // next iteration stores to the other Q buffer; no extra sync needed
    }
}

// ============================================================================
extern "C" void kernel_launch(void* const* d_in, const int* in_sizes, int n_in,
                              void* d_out, int out_size) {
    const float* q = (const float*)d_in[0];
    const float* k = (const float*)d_in[1];
    const float* v = (const float*)d_in[2];
    float* o = (float*)d_out;
    (void)in_sizes; (void)n_in; (void)out_size;

    cudaFuncSetAttribute(p1_kernel, cudaFuncAttributeMaxDynamicSharedMemorySize, P1_DSM);
    cudaFuncSetAttribute(p2_kernel, cudaFuncAttributeMaxDynamicSharedMemorySize, P2_DSM);

    p1_kernel<<<dim3(P1_CHUNKS, NH), 256, P1_DSM>>>(k, v);
    reduce_kernel<<<(NH * (KV_PITCH / 4) + 255) / 256, 256>>>();
    p2_kernel<<<dim3(Ll / 256, NH), 256, P2_DSM>>>(q, o);
}